// round 1
// baseline (speedup 1.0000x reference)
#include <cuda_runtime.h>
#include <cuda_bf16.h>
#include <math.h>

// Problem constants
#define NB    128      // batch
#define TCAP  31
#define TSTEP 30       // cap_in length
#define CIN   1280
#define WD    512
#define HD    1024
#define VOC   10000
#define NROW  (TSTEP*NB)   // 3840 rows for xa / hs / logits

// GEMM tiling
#define BM 64
#define BN 64
#define BK 16
#define PAD 4   // As row pad (stride 68 floats = 17*16B, keeps float4 alignment)

// ---------------- device scratch (static allocation is allowed) ----------------
__device__ float g_A[NB * 16 * HD];        // A[n][p][h]   8 MB
__device__ float g_hx[NB * 2 * HD];        // [h | attn]   1 MB
__device__ float g_c[NB * HD];
__device__ float g_a[NB * 4 * HD];         // LSTM pre-activations
__device__ float g_xa[NROW * 4 * HD];      // x@Wx + b, per (t,n)  63 MB
__device__ float g_hs[NROW * HD];          // all h_t             15.7 MB
__device__ float g_logits[NROW * VOC];     // 153.6 MB
__device__ float g_loss;

// ---------------- utility ----------------
__global__ void k_zero() { g_loss = 0.f; }

__global__ void k_final(float* __restrict__ out) {
    out[0] = g_loss * (1.0f / (float)NB);
}

// ---------------- 1) image projection GEMM ----------------
// A[(n,p)][h] = sum_c images[n][c][p] * W_proj[c][h] + b_proj[h]
// M=2048 rows (n*16+p), N=1024, K=1280
__global__ __launch_bounds__(256) void k_proj(const float* __restrict__ images,
                                              const float* __restrict__ Wp,
                                              const float* __restrict__ bp) {
    __shared__ float As[BK][BM + PAD];
    __shared__ float Bs[BK][BN];
    const int m0 = blockIdx.y * BM;
    const int n0 = blockIdx.x * BN;
    const int tid = threadIdx.x;
    const int tx = tid & 15, ty = tid >> 4;
    float acc[4][4] = {};

    const int m_l = tid >> 2, kq = tid & 3;
    const int n_l = tid & 63, k_l = tid >> 6;
    const int m = m0 + m_l;
    const int n_img = m >> 4, p = m & 15;
    const float* ib = images + n_img * (CIN * 16) + p;

    for (int k0 = 0; k0 < CIN; k0 += BK) {
#pragma unroll
        for (int d = 0; d < 4; d++) {
            int kk = kq * 4 + d;
            As[kk][m_l] = ib[(size_t)(k0 + kk) * 16];
        }
#pragma unroll
        for (int d = 0; d < 4; d++) {
            int kk = k_l + d * 4;
            Bs[kk][n_l] = Wp[(size_t)(k0 + kk) * HD + n0 + n_l];
        }
        __syncthreads();
#pragma unroll
        for (int kk = 0; kk < BK; kk++) {
            float4 av = *(const float4*)&As[kk][ty * 4];
            float4 bv = *(const float4*)&Bs[kk][tx * 4];
            float a[4] = {av.x, av.y, av.z, av.w};
            float b[4] = {bv.x, bv.y, bv.z, bv.w};
#pragma unroll
            for (int i = 0; i < 4; i++)
#pragma unroll
                for (int j = 0; j < 4; j++) acc[i][j] += a[i] * b[j];
        }
        __syncthreads();
    }
#pragma unroll
    for (int i = 0; i < 4; i++) {
        int mm = m0 + ty * 4 + i;
#pragma unroll
        for (int j = 0; j < 4; j++) {
            int nn = n0 + tx * 4 + j;
            g_A[(size_t)mm * HD + nn] = acc[i][j] + bp[nn];
        }
    }
}

// ---------------- 2) h0 = mean_p A, c0 = h0 ----------------
__global__ void k_h0() {
    int n = blockIdx.x;
    for (int h = threadIdx.x; h < HD; h += blockDim.x) {
        float s = 0.f;
#pragma unroll
        for (int p = 0; p < 16; p++) s += g_A[((size_t)n * 16 + p) * HD + h];
        s *= (1.0f / 16.0f);
        g_hx[(size_t)n * 2048 + h] = s;
        g_c[(size_t)n * HD + h] = s;
    }
}

// ---------------- 3) xa[(t,n)][j] = W_embed[cap[n][t]] @ Wx + b ----------------
// M=3840, N=4096, K=512 (row gather)
__global__ __launch_bounds__(256) void k_embed(const int* __restrict__ captions,
                                               const float* __restrict__ We,
                                               const float* __restrict__ Wx,
                                               const float* __restrict__ bvec) {
    __shared__ float As[BK][BM + PAD];
    __shared__ float Bs[BK][BN];
    __shared__ int idx_sh[BM];
    const int m0 = blockIdx.y * BM;
    const int n0 = blockIdx.x * BN;
    const int tid = threadIdx.x;
    const int tx = tid & 15, ty = tid >> 4;
    if (tid < BM) {
        int m = m0 + tid;
        int t = m >> 7, n = m & 127;
        idx_sh[tid] = captions[n * TCAP + t];
    }
    __syncthreads();
    float acc[4][4] = {};
    const int m_l = tid >> 2, kq = tid & 3;
    const int n_l = tid & 63, k_l = tid >> 6;
    const int row_idx = idx_sh[m_l];

    for (int k0 = 0; k0 < WD; k0 += BK) {
        float4 v = *(const float4*)&We[(size_t)row_idx * WD + k0 + kq * 4];
        As[kq * 4 + 0][m_l] = v.x;
        As[kq * 4 + 1][m_l] = v.y;
        As[kq * 4 + 2][m_l] = v.z;
        As[kq * 4 + 3][m_l] = v.w;
#pragma unroll
        for (int d = 0; d < 4; d++) {
            int kk = k_l + d * 4;
            Bs[kk][n_l] = Wx[(size_t)(k0 + kk) * (4 * HD) + n0 + n_l];
        }
        __syncthreads();
#pragma unroll
        for (int kk = 0; kk < BK; kk++) {
            float4 av = *(const float4*)&As[kk][ty * 4];
            float4 bv = *(const float4*)&Bs[kk][tx * 4];
            float a[4] = {av.x, av.y, av.z, av.w};
            float b[4] = {bv.x, bv.y, bv.z, bv.w};
#pragma unroll
            for (int i = 0; i < 4; i++)
#pragma unroll
                for (int j = 0; j < 4; j++) acc[i][j] += a[i] * b[j];
        }
        __syncthreads();
    }
#pragma unroll
    for (int i = 0; i < 4; i++) {
        int mm = m0 + ty * 4 + i;
#pragma unroll
        for (int j = 0; j < 4; j++) {
            int nn = n0 + tx * 4 + j;
            g_xa[(size_t)mm * (4 * HD) + nn] = acc[i][j] + bvec[nn];
        }
    }
}

// ---------------- 4a) attention ----------------
// one block per n, 512 threads
__global__ __launch_bounds__(512) void k_attn() {
    const int n = blockIdx.x;
    __shared__ float h_sh[HD];
    __shared__ float sc[16];
    const int tid = threadIdx.x;
    h_sh[tid] = g_hx[(size_t)n * 2048 + tid];
    h_sh[tid + 512] = g_hx[(size_t)n * 2048 + tid + 512];
    __syncthreads();
    const int w = tid >> 5, lane = tid & 31;
    {
        const float* Arow = g_A + ((size_t)n * 16 + w) * HD;
        float s = 0.f;
        for (int h = lane; h < HD; h += 32) s += h_sh[h] * Arow[h];
#pragma unroll
        for (int o = 16; o; o >>= 1) s += __shfl_xor_sync(0xFFFFFFFFu, s, o);
        if (lane == 0) sc[w] = s * 0.03125f;  // 1/sqrt(1024)
    }
    __syncthreads();
    float mx = sc[0];
#pragma unroll
    for (int p = 1; p < 16; p++) mx = fmaxf(mx, sc[p]);
    float wv[16];
    float sum = 0.f;
#pragma unroll
    for (int p = 0; p < 16; p++) { wv[p] = expf(sc[p] - mx); sum += wv[p]; }
    const float inv = 1.0f / sum;
    for (int h = tid; h < HD; h += 512) {
        float a = 0.f;
#pragma unroll
        for (int p = 0; p < 16; p++) a += wv[p] * g_A[((size_t)n * 16 + p) * HD + h];
        g_hx[(size_t)n * 2048 + HD + h] = a * inv;
    }
}

// ---------------- 4b) recurrent GEMM ----------------
// a[n][j] = xa[t][n][j] + sum_{k<2048} hx[n][k] * Whh[k][j]
// M=128, N=4096, K=2048 (Wh rows 0..1023, Wattn rows 1024..2047)
__global__ __launch_bounds__(256) void k_step(const float* __restrict__ Wh,
                                              const float* __restrict__ Wa, int t) {
    __shared__ float As[BK][BM + PAD];
    __shared__ float Bs[BK][BN];
    const int m0 = blockIdx.y * BM;
    const int n0 = blockIdx.x * BN;
    const int tid = threadIdx.x;
    const int tx = tid & 15, ty = tid >> 4;
    float acc[4][4] = {};
    const int m_l = tid >> 2, kq = tid & 3;
    const int n_l = tid & 63, k_l = tid >> 6;

    for (int k0 = 0; k0 < 2 * HD; k0 += BK) {
        const float* B = (k0 < HD) ? (Wh + (size_t)k0 * (4 * HD))
                                   : (Wa + (size_t)(k0 - HD) * (4 * HD));
        float4 v = *(const float4*)&g_hx[(size_t)(m0 + m_l) * 2048 + k0 + kq * 4];
        As[kq * 4 + 0][m_l] = v.x;
        As[kq * 4 + 1][m_l] = v.y;
        As[kq * 4 + 2][m_l] = v.z;
        As[kq * 4 + 3][m_l] = v.w;
#pragma unroll
        for (int d = 0; d < 4; d++) {
            int kk = k_l + d * 4;
            Bs[kk][n_l] = B[(size_t)kk * (4 * HD) + n0 + n_l];
        }
        __syncthreads();
#pragma unroll
        for (int kk = 0; kk < BK; kk++) {
            float4 av = *(const float4*)&As[kk][ty * 4];
            float4 bv = *(const float4*)&Bs[kk][tx * 4];
            float a[4] = {av.x, av.y, av.z, av.w};
            float b[4] = {bv.x, bv.y, bv.z, bv.w};
#pragma unroll
            for (int i = 0; i < 4; i++)
#pragma unroll
                for (int j = 0; j < 4; j++) acc[i][j] += a[i] * b[j];
        }
        __syncthreads();
    }
#pragma unroll
    for (int i = 0; i < 4; i++) {
        int mm = m0 + ty * 4 + i;
#pragma unroll
        for (int j = 0; j < 4; j++) {
            int nn = n0 + tx * 4 + j;
            g_a[(size_t)mm * (4 * HD) + nn] =
                acc[i][j] + g_xa[((size_t)t * NB + mm) * (4 * HD) + nn];
        }
    }
}

// ---------------- 4c) LSTM elementwise ----------------
__global__ void k_lstm(int t) {
    int idx = blockIdx.x * blockDim.x + threadIdx.x;  // n*HD + h
    if (idx >= NB * HD) return;
    int n = idx >> 10, h = idx & (HD - 1);
    const float* a = g_a + (size_t)n * (4 * HD);
    float iv = a[h], fv = a[HD + h], ov = a[2 * HD + h], gv = a[3 * HD + h];
    float si = 1.0f / (1.0f + expf(-iv));
    float sf = 1.0f / (1.0f + expf(-fv));
    float so = 1.0f / (1.0f + expf(-ov));
    float tg = tanhf(gv);
    float c = sf * g_c[idx] + si * tg;
    float hn = so * tanhf(c);
    g_c[idx] = c;
    g_hx[(size_t)n * 2048 + h] = hn;
    g_hs[((size_t)t * NB + n) * HD + h] = hn;
}

// ---------------- 5) logits GEMM ----------------
// M=3840, N=10000, K=1024
__global__ __launch_bounds__(256) void k_logits(const float* __restrict__ Wv,
                                                const float* __restrict__ bv) {
    __shared__ float As[BK][BM + PAD];
    __shared__ float Bs[BK][BN];
    const int m0 = blockIdx.y * BM;
    const int n0 = blockIdx.x * BN;
    const int tid = threadIdx.x;
    const int tx = tid & 15, ty = tid >> 4;
    float acc[4][4] = {};
    const int m_l = tid >> 2, kq = tid & 3;
    const int n_l = tid & 63, k_l = tid >> 6;
    const bool nok = (n0 + n_l) < VOC;

    for (int k0 = 0; k0 < HD; k0 += BK) {
        float4 v = *(const float4*)&g_hs[(size_t)(m0 + m_l) * HD + k0 + kq * 4];
        As[kq * 4 + 0][m_l] = v.x;
        As[kq * 4 + 1][m_l] = v.y;
        As[kq * 4 + 2][m_l] = v.z;
        As[kq * 4 + 3][m_l] = v.w;
#pragma unroll
        for (int d = 0; d < 4; d++) {
            int kk = k_l + d * 4;
            Bs[kk][n_l] = nok ? Wv[(size_t)(k0 + kk) * VOC + n0 + n_l] : 0.f;
        }
        __syncthreads();
#pragma unroll
        for (int kk = 0; kk < BK; kk++) {
            float4 av = *(const float4*)&As[kk][ty * 4];
            float4 bv4 = *(const float4*)&Bs[kk][tx * 4];
            float a[4] = {av.x, av.y, av.z, av.w};
            float b[4] = {bv4.x, bv4.y, bv4.z, bv4.w};
#pragma unroll
            for (int i = 0; i < 4; i++)
#pragma unroll
                for (int j = 0; j < 4; j++) acc[i][j] += a[i] * b[j];
        }
        __syncthreads();
    }
#pragma unroll
    for (int i = 0; i < 4; i++) {
        int mm = m0 + ty * 4 + i;
#pragma unroll
        for (int j = 0; j < 4; j++) {
            int nn = n0 + tx * 4 + j;
            if (nn < VOC)
                g_logits[(size_t)mm * VOC + nn] = acc[i][j] + bv[nn];
        }
    }
}

// ---------------- 6) streaming logsumexp + masked NLL ----------------
__global__ __launch_bounds__(256) void k_lsm(const int* __restrict__ captions) {
    const int m = blockIdx.x;          // (t,n) row
    const int t = m >> 7, n = m & 127;
    const int tid = threadIdx.x;
    const float* row = g_logits + (size_t)m * VOC;
    float mx = -INFINITY, s = 0.f;
    for (int v = tid; v < VOC; v += 256) {
        float x = row[v];
        if (x > mx) { s = s * expf(mx - x) + 1.f; mx = x; }
        else        { s += expf(x - mx); }
    }
    __shared__ float smx[256], ssm[256];
    smx[tid] = mx; ssm[tid] = s;
    __syncthreads();
    for (int o = 128; o; o >>= 1) {
        if (tid < o) {
            float m2 = smx[tid + o], s2 = ssm[tid + o];
            float M = fmaxf(smx[tid], m2);
            ssm[tid] = ssm[tid] * expf(smx[tid] - M) + s2 * expf(m2 - M);
            smx[tid] = M;
        }
        __syncthreads();
    }
    if (tid == 0) {
        int tgt = captions[n * TCAP + t + 1];
        if (tgt != 0) {  // NULL mask
            float lse = smx[0] + logf(ssm[0]);
            float nll = lse - row[tgt];
            atomicAdd(&g_loss, nll);
        }
    }
}

// ---------------- launch ----------------
extern "C" void kernel_launch(void* const* d_in, const int* in_sizes, int n_in,
                              void* d_out, int out_size) {
    const float* images  = (const float*)d_in[0];
    const int*   caps    = (const int*)  d_in[1];
    const float* W_embed = (const float*)d_in[2];
    const float* W_proj  = (const float*)d_in[3];
    const float* b_proj  = (const float*)d_in[4];
    const float* Wx      = (const float*)d_in[5];
    const float* Wh      = (const float*)d_in[6];
    const float* Wattn   = (const float*)d_in[7];
    const float* bvec    = (const float*)d_in[8];
    const float* W_vocab = (const float*)d_in[9];
    const float* b_vocab = (const float*)d_in[10];
    float* out = (float*)d_out;

    k_zero<<<1, 1>>>();
    k_proj<<<dim3(HD / BN, (NB * 16) / BM), 256>>>(images, W_proj, b_proj);
    k_h0<<<NB, 256>>>();
    k_embed<<<dim3((4 * HD) / BN, NROW / BM), 256>>>(caps, W_embed, Wx, bvec);
    for (int t = 0; t < TSTEP; t++) {
        k_attn<<<NB, 512>>>();
        k_step<<<dim3((4 * HD) / BN, NB / BM), 256>>>(Wh, Wattn, t);
        k_lstm<<<(NB * HD + 255) / 256, 256>>>(t);
    }
    k_logits<<<dim3((VOC + BN - 1) / BN, NROW / BM), 256>>>(W_vocab, b_vocab);
    k_lsm<<<NROW, 256>>>(caps);
    k_final<<<1, 1>>>(out);
}

// round 3
// speedup vs baseline: 5.2292x; 5.2292x over previous
#include <cuda_runtime.h>
#include <cuda_fp16.h>
#include <cstdint>
#include <math.h>

// ---------------- problem constants ----------------
#define NB    128
#define TCAP  31
#define TSTEP 30
#define CIN   1280
#define WD    512
#define HD    1024
#define VOC   10000
#define VOCP  10240
#define NROW  (TSTEP*NB)
#define KSPLIT 4

// ---------------- device scratch ----------------
__device__ float g_A[NB * 16 * HD];
__device__ float g_hx[NB * 2 * HD];
__device__ float g_c[NB * HD];
__device__ float g_xa[NROW * 4 * HD];
__device__ float g_apart[KSPLIT * NB * 4 * HD];
__device__ float g_logits[NROW * VOC];
__device__ float g_loss;

__device__ __align__(256) __half g_WpT[HD * CIN];          // [n=HD][k=CIN]
__device__ __align__(256) __half g_WxT[4 * HD * WD];       // [4HD][WD]
__device__ __align__(256) __half g_WhaT[4 * HD * 2 * HD];  // [4HD][2HD]  (Wh | Wattn)
__device__ __align__(256) __half g_WvT[VOCP * HD];         // [VOCP][HD], rows>=VOC zero
__device__ __align__(256) __half g_Ai[NB * 16 * CIN];      // image operand [2048][1280]
__device__ __align__(256) __half g_X[NROW * WD];           // embedded captions
__device__ __align__(256) __half g_hxh[NB * 2 * HD];       // [h | attn] fp16
__device__ __align__(256) __half g_hsh[NROW * HD];         // all h_t fp16

// ---------------- tiny utils ----------------
__global__ void k_zero() { g_loss = 0.f; }
__global__ void k_final(float* __restrict__ out) { out[0] = g_loss * (1.0f / (float)NB); }

__device__ __forceinline__ uint32_t smem_u32(const void* p) {
    uint32_t a;
    asm("{ .reg .u64 t; cvta.to.shared.u64 t, %1; cvt.u32.u64 %0, t; }" : "=r"(a) : "l"(p));
    return a;
}

// ---------------- weight transpose fp32[K][N] -> fp16[N][dld] at col offset koff ----------------
__global__ void k_convT(const float* __restrict__ src, int K, int N,
                        __half* __restrict__ dst, int dld, int koff) {
    __shared__ float t[32][33];
    const int nb = blockIdx.x * 32, kb = blockIdx.y * 32;
    const int tx = threadIdx.x, ty = threadIdx.y;
#pragma unroll
    for (int i = 0; i < 4; i++) {
        int k = kb + ty + i * 8, n = nb + tx;
        t[ty + i * 8][tx] = (n < N && k < K) ? src[(size_t)k * N + n] : 0.f;
    }
    __syncthreads();
#pragma unroll
    for (int i = 0; i < 4; i++) {
        int n = nb + ty + i * 8, k = kb + tx;
        dst[(size_t)n * dld + koff + k] = __float2half(t[tx][ty + i * 8]);
    }
}

// images (n,c,p) -> operand [m=n*16+p][c] fp16
__global__ void k_conv_images(const float* __restrict__ images) {
    int idx = blockIdx.x * blockDim.x + threadIdx.x;
    if (idx >= NB * 16 * CIN) return;
    int m = idx / CIN, c = idx - m * CIN;
    g_Ai[idx] = __float2half(images[((size_t)(m >> 4) * CIN + c) * 16 + (m & 15)]);
}

// embedding gather -> X[(t,n)][k] fp16
__global__ void k_conv_embed(const int* __restrict__ captions,
                             const float* __restrict__ We) {
    int idx = blockIdx.x * blockDim.x + threadIdx.x;
    if (idx >= NROW * WD) return;
    int m = idx / WD, k = idx - m * WD;
    int t = m >> 7, n = m & 127;
    g_X[idx] = __float2half(We[(size_t)captions[n * TCAP + t] * WD + k]);
}

// ---------------- fp16 mma.sync GEMM ----------------
// C[m][n] (+bias) = sum_k A[m][k] * B[n][k]
// BM=128, BN=128, BK=32, 256 thr (8 warps, 4x2 of 32x64 warp tiles)
// blockIdx.z = K slice, out += z*slice_stride
#define SROW 40   // smem row stride in halves (80 bytes: 5*16B, conflict-free ldmatrix)

__global__ __launch_bounds__(256) void k_gemm(
    const __half* __restrict__ Aop, const __half* __restrict__ Bop,
    int Kld, int Klen, const float* __restrict__ bias,
    float* __restrict__ out, int ldo, int Nvalid, size_t slice_stride) {
    __shared__ __align__(16) __half sm[2][2 * 128 * SROW];  // [stage][A(128*40) | B(128*40)]
    const int tid = threadIdx.x;
    const int wid = tid >> 5, lane = tid & 31;
    const int wm = (wid & 3) * 32;        // warp m offset
    const int wn = (wid >> 2) * 64;       // warp n offset
    const int m0 = blockIdx.y * 128;
    const int n0 = blockIdx.x * 128;
    const int koff = blockIdx.z * Klen;
    const int KT = Klen >> 5;

    const uint32_t sbase = smem_u32(sm);
    const int lrow = lane & 15, lcol = lane >> 4;

    float d[2][8][4];
#pragma unroll
    for (int i = 0; i < 2; i++)
#pragma unroll
        for (int j = 0; j < 8; j++)
#pragma unroll
            for (int q = 0; q < 4; q++) d[i][j][q] = 0.f;

    auto issue = [&](int kt) {
        const int stage = kt & 1;
        const uint32_t ab = sbase + (uint32_t)stage * (2 * 128 * SROW * 2);
        const uint32_t bb = ab + 128 * SROW * 2;
        const int k0 = koff + (kt << 5);
#pragma unroll
        for (int i = 0; i < 2; i++) {
            int c = tid + i * 256;                 // 512 chunks of 16B for A
            int r = c >> 2, seg = c & 3;
            const void* gp = Aop + (size_t)(m0 + r) * Kld + k0 + seg * 8;
            uint32_t sp = ab + (uint32_t)(r * SROW * 2 + seg * 16);
            asm volatile("cp.async.cg.shared.global [%0], [%1], 16;" :: "r"(sp), "l"(gp));
        }
#pragma unroll
        for (int i = 0; i < 2; i++) {
            int c = tid + i * 256;
            int r = c >> 2, seg = c & 3;
            const void* gp = Bop + (size_t)(n0 + r) * Kld + k0 + seg * 8;
            uint32_t sp = bb + (uint32_t)(r * SROW * 2 + seg * 16);
            asm volatile("cp.async.cg.shared.global [%0], [%1], 16;" :: "r"(sp), "l"(gp));
        }
        asm volatile("cp.async.commit_group;");
    };

    issue(0);
    for (int kt = 0; kt < KT; kt++) {
        if (kt + 1 < KT) {
            issue(kt + 1);
            asm volatile("cp.async.wait_group 1;");
        } else {
            asm volatile("cp.async.wait_group 0;");
        }
        __syncthreads();
        const int stage = kt & 1;
        const uint32_t ab = sbase + (uint32_t)stage * (2 * 128 * SROW * 2);
        const uint32_t bb = ab + 128 * SROW * 2;
#pragma unroll
        for (int ks = 0; ks < 2; ks++) {
            uint32_t af[2][4];
#pragma unroll
            for (int mi = 0; mi < 2; mi++) {
                uint32_t addr = ab + (uint32_t)((wm + mi * 16 + lrow) * SROW * 2
                                                + lcol * 16 + ks * 32);
                asm volatile("ldmatrix.sync.aligned.m8n8.x4.shared.b16 {%0,%1,%2,%3}, [%4];"
                             : "=r"(af[mi][0]), "=r"(af[mi][1]), "=r"(af[mi][2]), "=r"(af[mi][3])
                             : "r"(addr));
            }
#pragma unroll
            for (int bj = 0; bj < 4; bj++) {
                uint32_t bf[4];
                uint32_t addr = bb + (uint32_t)((wn + bj * 16 + lrow) * SROW * 2
                                                + lcol * 16 + ks * 32);
                asm volatile("ldmatrix.sync.aligned.m8n8.x4.trans.shared.b16 {%0,%1,%2,%3}, [%4];"
                             : "=r"(bf[0]), "=r"(bf[1]), "=r"(bf[2]), "=r"(bf[3])
                             : "r"(addr));
#pragma unroll
                for (int mi = 0; mi < 2; mi++) {
                    asm volatile(
                        "mma.sync.aligned.m16n8k16.row.col.f32.f16.f16.f32 "
                        "{%0,%1,%2,%3}, {%4,%5,%6,%7}, {%8,%9}, {%0,%1,%2,%3};"
                        : "+f"(d[mi][bj * 2][0]), "+f"(d[mi][bj * 2][1]),
                          "+f"(d[mi][bj * 2][2]), "+f"(d[mi][bj * 2][3])
                        : "r"(af[mi][0]), "r"(af[mi][1]), "r"(af[mi][2]), "r"(af[mi][3]),
                          "r"(bf[0]), "r"(bf[2]));
                    asm volatile(
                        "mma.sync.aligned.m16n8k16.row.col.f32.f16.f16.f32 "
                        "{%0,%1,%2,%3}, {%4,%5,%6,%7}, {%8,%9}, {%0,%1,%2,%3};"
                        : "+f"(d[mi][bj * 2 + 1][0]), "+f"(d[mi][bj * 2 + 1][1]),
                          "+f"(d[mi][bj * 2 + 1][2]), "+f"(d[mi][bj * 2 + 1][3])
                        : "r"(af[mi][0]), "r"(af[mi][1]), "r"(af[mi][2]), "r"(af[mi][3]),
                          "r"(bf[1]), "r"(bf[3]));
                }
            }
        }
        __syncthreads();
    }

    // epilogue
    const int gid = lane >> 2, qid = lane & 3;
    float* obase = out + slice_stride * blockIdx.z;
#pragma unroll
    for (int mi = 0; mi < 2; mi++) {
        int r0 = m0 + wm + mi * 16 + gid;
#pragma unroll
        for (int nj = 0; nj < 8; nj++) {
            int col = n0 + wn + nj * 8 + qid * 2;
            if (col < Nvalid) {
                float b0 = bias ? bias[col] : 0.f;
                float b1 = bias ? bias[col + 1] : 0.f;
                float2 v0 = make_float2(d[mi][nj][0] + b0, d[mi][nj][1] + b1);
                float2 v1 = make_float2(d[mi][nj][2] + b0, d[mi][nj][3] + b1);
                *(float2*)&obase[(size_t)r0 * ldo + col] = v0;
                *(float2*)&obase[(size_t)(r0 + 8) * ldo + col] = v1;
            }
        }
    }
}

// ---------------- h0 = mean_p A ----------------
__global__ void k_h0() {
    int n = blockIdx.x;
    for (int h = threadIdx.x; h < HD; h += blockDim.x) {
        float s = 0.f;
#pragma unroll
        for (int p = 0; p < 16; p++) s += g_A[((size_t)n * 16 + p) * HD + h];
        s *= (1.0f / 16.0f);
        g_hx[(size_t)n * 2048 + h] = s;
        g_c[(size_t)n * HD + h] = s;
        g_hxh[(size_t)n * 2048 + h] = __float2half(s);
    }
}

// ---------------- attention (fp32) ----------------
__global__ __launch_bounds__(512) void k_attn() {
    const int n = blockIdx.x;
    __shared__ float h_sh[HD];
    __shared__ float sc[16];
    const int tid = threadIdx.x;
    h_sh[tid] = g_hx[(size_t)n * 2048 + tid];
    h_sh[tid + 512] = g_hx[(size_t)n * 2048 + tid + 512];
    __syncthreads();
    const int w = tid >> 5, lane = tid & 31;
    {
        const float* Arow = g_A + ((size_t)n * 16 + w) * HD;
        float s = 0.f;
        for (int h = lane; h < HD; h += 32) s += h_sh[h] * Arow[h];
#pragma unroll
        for (int o = 16; o; o >>= 1) s += __shfl_xor_sync(0xFFFFFFFFu, s, o);
        if (lane == 0) sc[w] = s * 0.03125f;
    }
    __syncthreads();
    float mx = sc[0];
#pragma unroll
    for (int p = 1; p < 16; p++) mx = fmaxf(mx, sc[p]);
    float wv[16];
    float sum = 0.f;
#pragma unroll
    for (int p = 0; p < 16; p++) { wv[p] = expf(sc[p] - mx); sum += wv[p]; }
    const float inv = 1.0f / sum;
    for (int h = tid; h < HD; h += 512) {
        float a = 0.f;
#pragma unroll
        for (int p = 0; p < 16; p++) a += wv[p] * g_A[((size_t)n * 16 + p) * HD + h];
        float av = a * inv;
        size_t o = (size_t)n * 2048 + HD + h;
        g_hx[o] = av;
        g_hxh[o] = __float2half(av);
    }
}

// ---------------- LSTM elementwise (+ split-K reduce) ----------------
__global__ void k_lstm(int t) {
    int idx = blockIdx.x * blockDim.x + threadIdx.x;
    if (idx >= NB * HD) return;
    int n = idx >> 10, h = idx & (HD - 1);
    float a0 = 0.f, a1 = 0.f, a2 = 0.f, a3 = 0.f;
#pragma unroll
    for (int s = 0; s < KSPLIT; s++) {
        const float* p = g_apart + (size_t)s * NB * 4096 + (size_t)n * 4096;
        a0 += p[h]; a1 += p[HD + h]; a2 += p[2 * HD + h]; a3 += p[3 * HD + h];
    }
    const float* xa = g_xa + ((size_t)t * NB + n) * 4096;
    a0 += xa[h]; a1 += xa[HD + h]; a2 += xa[2 * HD + h]; a3 += xa[3 * HD + h];
    float si = 1.0f / (1.0f + expf(-a0));
    float sf = 1.0f / (1.0f + expf(-a1));
    float so = 1.0f / (1.0f + expf(-a2));
    float tg = tanhf(a3);
    float c = sf * g_c[idx] + si * tg;
    float hn = so * tanhf(c);
    g_c[idx] = c;
    g_hx[(size_t)n * 2048 + h] = hn;
    g_hxh[(size_t)n * 2048 + h] = __float2half(hn);
    g_hsh[((size_t)t * NB + n) * HD + h] = __float2half(hn);
}

// ---------------- streaming logsumexp + masked NLL ----------------
__global__ __launch_bounds__(256) void k_lsm(const int* __restrict__ captions) {
    const int m = blockIdx.x;
    const int t = m >> 7, n = m & 127;
    const int tid = threadIdx.x;
    const float* row = g_logits + (size_t)m * VOC;
    float mx = -INFINITY, s = 0.f;
    for (int v = tid; v < VOC; v += 256) {
        float x = row[v];
        if (x > mx) { s = s * expf(mx - x) + 1.f; mx = x; }
        else        { s += expf(x - mx); }
    }
    __shared__ float smx[256], ssm[256];
    smx[tid] = mx; ssm[tid] = s;
    __syncthreads();
    for (int o = 128; o; o >>= 1) {
        if (tid < o) {
            float m2 = smx[tid + o], s2 = ssm[tid + o];
            float M = fmaxf(smx[tid], m2);
            ssm[tid] = ssm[tid] * expf(smx[tid] - M) + s2 * expf(m2 - M);
            smx[tid] = M;
        }
        __syncthreads();
    }
    if (tid == 0) {
        int tgt = captions[n * TCAP + t + 1];
        if (tgt != 0) {
            float lse = smx[0] + logf(ssm[0]);
            atomicAdd(&g_loss, lse - row[tgt]);
        }
    }
}

// ---------------- launch ----------------
extern "C" void kernel_launch(void* const* d_in, const int* in_sizes, int n_in,
                              void* d_out, int out_size) {
    const float* images  = (const float*)d_in[0];
    const int*   caps    = (const int*)  d_in[1];
    const float* W_embed = (const float*)d_in[2];
    const float* W_proj  = (const float*)d_in[3];
    const float* b_proj  = (const float*)d_in[4];
    const float* Wx      = (const float*)d_in[5];
    const float* Wh      = (const float*)d_in[6];
    const float* Wattn   = (const float*)d_in[7];
    const float* bvec    = (const float*)d_in[8];
    const float* W_vocab = (const float*)d_in[9];
    const float* b_vocab = (const float*)d_in[10];
    float* out = (float*)d_out;

    float *pA, *pXa, *pApart, *pLogits;
    cudaGetSymbolAddress((void**)&pA, g_A);
    cudaGetSymbolAddress((void**)&pXa, g_xa);
    cudaGetSymbolAddress((void**)&pApart, g_apart);
    cudaGetSymbolAddress((void**)&pLogits, g_logits);
    __half *pWp, *pWx, *pWha, *pWv, *pAi, *pX, *pHxh, *pHsh;
    cudaGetSymbolAddress((void**)&pWp, g_WpT);
    cudaGetSymbolAddress((void**)&pWx, g_WxT);
    cudaGetSymbolAddress((void**)&pWha, g_WhaT);
    cudaGetSymbolAddress((void**)&pWv, g_WvT);
    cudaGetSymbolAddress((void**)&pAi, g_Ai);
    cudaGetSymbolAddress((void**)&pX, g_X);
    cudaGetSymbolAddress((void**)&pHxh, g_hxh);
    cudaGetSymbolAddress((void**)&pHsh, g_hsh);

    dim3 b32(32, 8);
    k_zero<<<1, 1>>>();
    // weight conversions (transpose to [N][K] fp16)
    k_convT<<<dim3(HD / 32, CIN / 32), b32>>>(W_proj, CIN, HD, pWp, CIN, 0);
    k_convT<<<dim3(4 * HD / 32, WD / 32), b32>>>(Wx, WD, 4 * HD, pWx, WD, 0);
    k_convT<<<dim3(4 * HD / 32, HD / 32), b32>>>(Wh, HD, 4 * HD, pWha, 2 * HD, 0);
    k_convT<<<dim3(4 * HD / 32, HD / 32), b32>>>(Wattn, HD, 4 * HD, pWha, 2 * HD, HD);
    k_convT<<<dim3(VOCP / 32, HD / 32), b32>>>(W_vocab, HD, VOC, pWv, HD, 0);
    k_conv_images<<<(NB * 16 * CIN + 255) / 256, 256>>>(images);
    k_conv_embed<<<(NROW * WD + 255) / 256, 256>>>(caps, W_embed);

    // image projection: [2048 x 1024] = Ai[2048 x 1280] @ WpT^T + b_proj
    k_gemm<<<dim3(HD / 128, (NB * 16) / 128, 1), 256>>>(
        pAi, pWp, CIN, CIN, b_proj, pA, HD, HD, 0);
    k_h0<<<NB, 256>>>();

    // xa: [3840 x 4096] = X[3840 x 512] @ WxT^T + b
    k_gemm<<<dim3(4 * HD / 128, NROW / 128, 1), 256>>>(
        pX, pWx, WD, WD, bvec, pXa, 4 * HD, 4 * HD, 0);

    for (int t = 0; t < TSTEP; t++) {
        k_attn<<<NB, 512>>>();
        // a_part[z]: [128 x 4096] = hx[128 x 2048] @ WhaT^T, split-K=4
        k_gemm<<<dim3(4 * HD / 128, 1, KSPLIT), 256>>>(
            pHxh, pWha, 2 * HD, 2 * HD / KSPLIT, nullptr,
            pApart, 4 * HD, 4 * HD, (size_t)NB * 4 * HD);
        k_lstm<<<(NB * HD + 255) / 256, 256>>>(t);
    }

    // logits: [3840 x 10000] = hs[3840 x 1024] @ WvT^T + b
    k_gemm<<<dim3(VOCP / 128, NROW / 128, 1), 256>>>(
        pHsh, pWv, HD, HD, b_vocab, pLogits, VOC, VOC, 0);

    k_lsm<<<NROW, 256>>>(caps);
    k_final<<<1, 1>>>(out);
}